// round 1
// baseline (speedup 1.0000x reference)
#include <cuda_runtime.h>
#include <math.h>

#define BB 4
#define CC 64
#define HH 128
#define WW 128
#define OO 64
#define HW (HH*WW)          // 16384
#define NPOS (BB*HW)        // 65536

// -------- scratch (device globals; no allocation allowed) --------
__device__ float g_xt[BB*HH*WW*CC];        // x transposed to [b][h][w][c]
__device__ float g_om[(size_t)NPOS*27];    // offsets(18) + sigmoid(mask)(9), NHWC
__device__ float g_wr[9*CC*OO];            // weight reordered [tap][c][o]
__device__ float g_sum[OO];
__device__ float g_sq[OO];
__device__ float g_scale[OO];
__device__ float g_shift[OO];

// ---------------- Kernel A: transpose + weight reorder + zero stats ----------------
__global__ void prep_kernel(const float* __restrict__ x,
                            const float* __restrict__ weight) {
    __shared__ float s[CC*129];
    int b = blockIdx.x >> 7;
    int h = blockIdx.x & 127;
    int tid = threadIdx.x;
    for (int i = tid; i < CC*WW; i += 256) {
        int c = i >> 7, w = i & 127;
        s[c*129 + w] = x[((b*CC + c)*HH + h)*WW + w];
    }
    __syncthreads();
    for (int i = tid; i < WW*CC; i += 256) {
        int w = i >> 6, c = i & 63;
        g_xt[(((b*HH) + h)*WW + w)*CC + c] = s[c*129 + w];
    }
    if (blockIdx.x == 0) {
        // reorder main conv weight [O][C][3][3] -> [tap][c][o]
        for (int i = tid; i < 9*CC*OO; i += 256) {
            int o = i / (CC*9);
            int r = i % (CC*9);
            int c = r / 9;
            int t = r % 9;
            g_wr[(t*CC + c)*OO + o] = weight[i];
        }
        if (tid < OO) { g_sum[tid] = 0.f; g_sq[tid] = 0.f; }
    }
}

// ---------------- Kernel B: 3x3 offset/mask conv (27 out channels) ----------------
__global__ __launch_bounds__(256) void offset_conv_kernel(
        const float* __restrict__ x,
        const float* __restrict__ ow,
        const float* __restrict__ ob) {
    extern __shared__ float ws[];  // [c*9+t][28] (27 outputs + 1 pad for float4)
    int tid = threadIdx.x;
    for (int i = tid; i < 27*576; i += 256) {
        int j = i / 576, r = i % 576;       // r = c*9 + t
        ws[r*28 + j] = ow[i];
    }
    for (int i = tid; i < 576; i += 256) ws[i*28 + 27] = 0.f;
    __syncthreads();

    int pos = blockIdx.x*256 + tid;
    int b = pos >> 14, p = pos & 16383;
    int h = p >> 7, w = p & 127;

    float acc[28];
    #pragma unroll
    for (int j = 0; j < 28; j++) acc[j] = 0.f;

    const float* xb = x + (size_t)b*CC*HW;
    #pragma unroll 1
    for (int t = 0; t < 9; t++) {
        int y = h + t/3 - 1, xw = w + t%3 - 1;
        if ((unsigned)y < HH && (unsigned)xw < WW) {
            const float* xp = xb + y*WW + xw;
            #pragma unroll 4
            for (int c = 0; c < CC; c++) {
                float v = __ldg(xp + c*HW);
                const float4* wp = (const float4*)&ws[(c*9 + t)*28];
                #pragma unroll
                for (int q = 0; q < 7; q++) {
                    float4 wv = wp[q];
                    acc[q*4+0] += v*wv.x;
                    acc[q*4+1] += v*wv.y;
                    acc[q*4+2] += v*wv.z;
                    acc[q*4+3] += v*wv.w;
                }
            }
        }
    }
    float* omp = &g_om[(size_t)pos*27];
    #pragma unroll
    for (int j = 0; j < 27; j++) {
        float v = acc[j] + __ldg(&ob[j]);
        if (j >= 18) v = 1.f/(1.f + __expf(-v));   // sigmoid for mask channels
        omp[j] = v;
    }
}

// ---------------- Kernel C: fused deformable gather + GEMM + stat partials ----------------
// Block: 256 threads, tile = 64 consecutive spatial positions of one image,
// computes all 64 output channels. K-chunked by tap (9 chunks of 64 channels).
__global__ __launch_bounds__(256) void main_kernel(const float* __restrict__ bias,
                                                   float* __restrict__ out) {
    __shared__ float val_s[CC*68];      // [c][pos], pitch 68 (16B-aligned rows)
    __shared__ float w2_s[CC*OO];       // [c][o] for current tap
    __shared__ float s_sum[OO], s_sq[OO];

    int t = threadIdx.x;
    int b = blockIdx.x >> 8;
    int tile = blockIdx.x & 255;
    int p0 = tile * 64;

    // gather role: thread -> (pos j, channel group of 16)
    int j = t & 63;
    int cg = (t >> 6) * 16;
    int p = p0 + j;
    int h = p >> 7, w = p & 127;
    const float* omp = &g_om[((size_t)b*HW + p)*27];
    const float* xtb = g_xt + (size_t)b*HW*CC;

    // gemm role: thread -> 4 o x 4 pos
    int tx = t & 15, ty = t >> 4;
    float acc[4][4];
    #pragma unroll
    for (int a = 0; a < 4; a++)
        #pragma unroll
        for (int q = 0; q < 4; q++) acc[a][q] = 0.f;

    if (t < OO) { s_sum[t] = 0.f; s_sq[t] = 0.f; }

    #pragma unroll 1
    for (int tap = 0; tap < 9; tap++) {
        __syncthreads();  // protect smem reuse (and stat init on iter 0)

        // stage this tap's weights [c][o]
        {
            const float4* wsrc = (const float4*)&g_wr[tap*CC*OO];
            float4* wdst = (float4*)w2_s;
            #pragma unroll
            for (int i = 0; i < 4; i++) wdst[t + i*256] = wsrc[t + i*256];
        }

        // gather this tap's val tile into smem
        {
            float dy = omp[2*tap], dx = omp[2*tap+1], m = omp[18+tap];
            float ysf = (float)(h - 1 + tap/3) + dy;
            float xsf = (float)(w - 1 + tap%3) + dx;
            float y0f = floorf(ysf), x0f = floorf(xsf);
            float fy = ysf - y0f, fx = xsf - x0f;
            int y0 = (int)y0f, x0 = (int)x0f;
            int y1 = y0 + 1, x1 = x0 + 1;
            float gy = 1.f - fy, gx = 1.f - fx;
            float w00 = gy*gx*m, w01 = gy*fx*m, w10 = fy*gx*m, w11 = fy*fx*m;
            bool vy0 = (unsigned)y0 < HH, vy1 = (unsigned)y1 < HH;
            bool vx0 = (unsigned)x0 < WW, vx1 = (unsigned)x1 < WW;
            w00 = (vy0 && vx0) ? w00 : 0.f;
            w01 = (vy0 && vx1) ? w01 : 0.f;
            w10 = (vy1 && vx0) ? w10 : 0.f;
            w11 = (vy1 && vx1) ? w11 : 0.f;
            int cy0 = min(max(y0, 0), HH-1), cy1 = min(max(y1, 0), HH-1);
            int cx0 = min(max(x0, 0), WW-1), cx1 = min(max(x1, 0), WW-1);
            const float4* q00 = (const float4*)(xtb + (cy0*WW + cx0)*CC + cg);
            const float4* q01 = (const float4*)(xtb + (cy0*WW + cx1)*CC + cg);
            const float4* q10 = (const float4*)(xtb + (cy1*WW + cx0)*CC + cg);
            const float4* q11 = (const float4*)(xtb + (cy1*WW + cx1)*CC + cg);
            #pragma unroll
            for (int q = 0; q < 4; q++) {
                float4 a0 = q00[q], a1 = q01[q], a2 = q10[q], a3 = q11[q];
                int c = cg + q*4;
                val_s[(c+0)*68 + j] = w00*a0.x + w01*a1.x + w10*a2.x + w11*a3.x;
                val_s[(c+1)*68 + j] = w00*a0.y + w01*a1.y + w10*a2.y + w11*a3.y;
                val_s[(c+2)*68 + j] = w00*a0.z + w01*a1.z + w10*a2.z + w11*a3.z;
                val_s[(c+3)*68 + j] = w00*a0.w + w01*a1.w + w10*a2.w + w11*a3.w;
            }
        }
        __syncthreads();

        // 64x64 += 64x64c outer-product GEMM, 4x4 per thread
        #pragma unroll
        for (int c = 0; c < CC; c++) {
            float4 av = *(const float4*)&w2_s[c*OO + ty*4];
            float4 bv = *(const float4*)&val_s[c*68 + tx*4];
            acc[0][0] += av.x*bv.x; acc[0][1] += av.x*bv.y; acc[0][2] += av.x*bv.z; acc[0][3] += av.x*bv.w;
            acc[1][0] += av.y*bv.x; acc[1][1] += av.y*bv.y; acc[1][2] += av.y*bv.z; acc[1][3] += av.y*bv.w;
            acc[2][0] += av.z*bv.x; acc[2][1] += av.z*bv.y; acc[2][2] += av.z*bv.z; acc[2][3] += av.z*bv.w;
            acc[3][0] += av.w*bv.x; acc[3][1] += av.w*bv.y; acc[3][2] += av.w*bv.z; acc[3][3] += av.w*bv.w;
        }
    }

    // epilogue: bias, store pre-BN, partial sums for batch stats
    int o0 = ty*4;
    #pragma unroll
    for (int oi = 0; oi < 4; oi++) {
        float bsv = __ldg(&bias[o0+oi]);
        float4 v;
        v.x = acc[oi][0] + bsv;
        v.y = acc[oi][1] + bsv;
        v.z = acc[oi][2] + bsv;
        v.w = acc[oi][3] + bsv;
        *(float4*)&out[((size_t)(b*OO + o0+oi))*HW + p0 + tx*4] = v;
        float s = v.x + v.y + v.z + v.w;
        float q = v.x*v.x + v.y*v.y + v.z*v.z + v.w*v.w;
        #pragma unroll
        for (int off = 8; off >= 1; off >>= 1) {
            s += __shfl_down_sync(0xffffffffu, s, off, 16);
            q += __shfl_down_sync(0xffffffffu, q, off, 16);
        }
        if (tx == 0) { atomicAdd(&s_sum[o0+oi], s); atomicAdd(&s_sq[o0+oi], q); }
    }
    __syncthreads();
    if (t < OO) { atomicAdd(&g_sum[t], s_sum[t]); atomicAdd(&g_sq[t], s_sq[t]); }
}

// ---------------- Kernel D: finalize BN stats ----------------
__global__ void stats_kernel(const float* __restrict__ gamma,
                             const float* __restrict__ beta) {
    int o = threadIdx.x;
    float n = (float)NPOS;
    float mean = g_sum[o] / n;
    float var  = g_sq[o] / n - mean*mean;
    float sc = gamma[o] * rsqrtf(var + 1e-5f);
    g_scale[o] = sc;
    g_shift[o] = beta[o] - mean*sc;
}

// ---------------- Kernel E: BN apply + ReLU (in-place on d_out) ----------------
__global__ void bn_relu_kernel(float* __restrict__ out) {
    int i = blockIdx.x*blockDim.x + threadIdx.x;   // float4 index
    if (i < (BB*OO*HW)/4) {
        float4 v = ((float4*)out)[i];
        int o = ((i*4) >> 14) & 63;
        float sc = g_scale[o], sh = g_shift[o];
        v.x = fmaxf(fmaf(v.x, sc, sh), 0.f);
        v.y = fmaxf(fmaf(v.y, sc, sh), 0.f);
        v.z = fmaxf(fmaf(v.z, sc, sh), 0.f);
        v.w = fmaxf(fmaf(v.w, sc, sh), 0.f);
        ((float4*)out)[i] = v;
    }
}

extern "C" void kernel_launch(void* const* d_in, const int* in_sizes, int n_in,
                              void* d_out, int out_size) {
    const float* x  = (const float*)d_in[0];
    const float* ow = (const float*)d_in[1];
    const float* ob = (const float*)d_in[2];
    const float* wt = (const float*)d_in[3];
    const float* bs = (const float*)d_in[4];
    const float* gm = (const float*)d_in[5];
    const float* bt = (const float*)d_in[6];
    float* out = (float*)d_out;

    // offset conv needs 63 KB dynamic smem (576*28 floats)
    cudaFuncSetAttribute(offset_conv_kernel,
                         cudaFuncAttributeMaxDynamicSharedMemorySize, 576*28*4);

    prep_kernel<<<BB*HH, 256>>>(x, wt);
    offset_conv_kernel<<<NPOS/256, 256, 576*28*4>>>(x, ow, ob);
    main_kernel<<<BB*256, 256>>>(bs, out);
    stats_kernel<<<1, OO>>>(gm, bt);
    bn_relu_kernel<<<(BB*OO*HW/4 + 255)/256, 256>>>(out);
}

// round 4
// speedup vs baseline: 1.8213x; 1.8213x over previous
#include <cuda_runtime.h>
#include <math.h>
#include <stdint.h>

#define BB 4
#define CC 64
#define HH 128
#define WW 128
#define OO 64
#define HW (HH*WW)          // 16384
#define NPOS (BB*HW)        // 65536

#define A_PITCH 68          // floats; 68 mod 32 = 4 -> conflict-free A frags
#define B_PITCH 72          // floats; 72 mod 32 = 8 -> conflict-free B frags
#define SMEM_FLOATS (128*A_PITCH + 64*B_PITCH)   // 8704 + 4608 = 13312 -> 53248 B

// -------- scratch (device globals; no allocation allowed) --------
__device__ float g_xt[BB*HH*WW*CC];        // x transposed to [b][h][w][c]
__device__ float g_om[(size_t)NPOS*27];    // offsets(18) + sigmoid(mask)(9), per-pos
__device__ float g_wr[9*CC*OO];            // weight reordered [tap][c][o], tf32-rounded
__device__ float g_sum[OO];
__device__ float g_sq[OO];
__device__ float g_scale[OO];
__device__ float g_shift[OO];

__device__ __forceinline__ uint32_t f2tf32(float f) {
    uint32_t u;
    asm("cvt.rna.tf32.f32 %0, %1;" : "=r"(u) : "f"(f));
    return u;
}

__device__ __forceinline__ void mma8(float* d, const uint32_t* a, const uint32_t* b) {
    asm volatile(
        "mma.sync.aligned.m16n8k8.row.col.f32.tf32.tf32.f32 "
        "{%0,%1,%2,%3}, {%4,%5,%6,%7}, {%8,%9}, {%0,%1,%2,%3};"
        : "+f"(d[0]), "+f"(d[1]), "+f"(d[2]), "+f"(d[3])
        : "r"(a[0]), "r"(a[1]), "r"(a[2]), "r"(a[3]), "r"(b[0]), "r"(b[1]));
}

// ---------------- Kernel A: transpose + weight reorder + zero stats ----------------
__global__ void prep_kernel(const float* __restrict__ x,
                            const float* __restrict__ weight) {
    __shared__ float s[CC*129];
    int b = blockIdx.x >> 7;
    int h = blockIdx.x & 127;
    int tid = threadIdx.x;
    for (int i = tid; i < CC*WW; i += 256) {
        int c = i >> 7, w = i & 127;
        s[c*129 + w] = x[((b*CC + c)*HH + h)*WW + w];
    }
    __syncthreads();
    for (int i = tid; i < WW*CC; i += 256) {
        int w = i >> 6, c = i & 63;
        g_xt[(((b*HH) + h)*WW + w)*CC + c] = s[c*129 + w];
    }
    if (blockIdx.x == 0) {
        // reorder main conv weight [O][C][3][3] -> [tap][c][o], tf32-rounded
        for (int i = tid; i < 9*CC*OO; i += 256) {
            int o = i / (CC*9);
            int r = i % (CC*9);
            int c = r / 9;
            int t = r % 9;
            g_wr[(t*CC + c)*OO + o] = __uint_as_float(f2tf32(weight[i]));
        }
        if (tid < OO) { g_sum[tid] = 0.f; g_sq[tid] = 0.f; }
    }
}

// ---------------- Kernel B: 3x3 offset/mask conv (27 out channels) ----------------
__global__ __launch_bounds__(256) void offset_conv_kernel(
        const float* __restrict__ x,
        const float* __restrict__ ow,
        const float* __restrict__ ob) {
    extern __shared__ float ws[];  // [c*9+t][28]
    int tid = threadIdx.x;
    for (int i = tid; i < 27*576; i += 256) {
        int j = i / 576, r = i % 576;
        ws[r*28 + j] = ow[i];
    }
    for (int i = tid; i < 576; i += 256) ws[i*28 + 27] = 0.f;
    __syncthreads();

    int pos = blockIdx.x*256 + tid;
    int b = pos >> 14, p = pos & 16383;
    int h = p >> 7, w = p & 127;

    float acc[28];
    #pragma unroll
    for (int j = 0; j < 28; j++) acc[j] = 0.f;

    const float* xb = x + (size_t)b*CC*HW;
    #pragma unroll 1
    for (int t = 0; t < 9; t++) {
        int y = h + t/3 - 1, xw = w + t%3 - 1;
        if ((unsigned)y < HH && (unsigned)xw < WW) {
            const float* xp = xb + y*WW + xw;
            #pragma unroll 4
            for (int c = 0; c < CC; c++) {
                float v = __ldg(xp + c*HW);
                const float4* wp = (const float4*)&ws[(c*9 + t)*28];
                #pragma unroll
                for (int q = 0; q < 7; q++) {
                    float4 wv = wp[q];
                    acc[q*4+0] += v*wv.x;
                    acc[q*4+1] += v*wv.y;
                    acc[q*4+2] += v*wv.z;
                    acc[q*4+3] += v*wv.w;
                }
            }
        }
    }
    float* omp = &g_om[(size_t)pos*27];
    #pragma unroll
    for (int j = 0; j < 27; j++) {
        float v = acc[j] + __ldg(&ob[j]);
        if (j >= 18) v = 1.f/(1.f + __expf(-v));
        omp[j] = v;
    }
}

// ---------------- Kernel C: deformable gather + mma.sync tf32 GEMM ----------------
// One CTA = one image row (128 positions) x all 64 output channels.
// As: [128 pos][64 ch] pitch 68; Bs: [64 c][64 o] pitch 72 (per tap).
// 8 warps in 4x2: warp tile 32 pos x 32 o, m16n8k8 tf32 fragments.
__global__ __launch_bounds__(256, 2) void main_kernel(const float* __restrict__ bias,
                                                      float* __restrict__ out) {
    extern __shared__ float sm[];
    float* As = sm;                  // 128*68 floats
    float* Bs = sm + 128*A_PITCH;    // 64*72 floats

    int t = threadIdx.x;
    int wid = t >> 5, lane = t & 31;
    int b = blockIdx.x >> 7;
    int h = blockIdx.x & 127;
    int p0 = h * 128;

    // gather role: warp -> 16 positions, lane -> (pos parity, channel group)
    int pp = lane >> 4;          // 0..1
    int cl = lane & 15;          // channel group: floats cl*4..cl*4+3
    const float* xtb = g_xt + (size_t)b*HW*CC;

    // gemm role
    int m0 = (wid & 3) * 32;
    int n0 = (wid >> 2) * 32;
    int gid = lane >> 2, tig = lane & 3;

    float acc[2][4][4];
    #pragma unroll
    for (int mt = 0; mt < 2; mt++)
        #pragma unroll
        for (int nt = 0; nt < 4; nt++)
            #pragma unroll
            for (int q = 0; q < 4; q++) acc[mt][nt][q] = 0.f;

    #pragma unroll 1
    for (int tap = 0; tap < 9; tap++) {
        __syncthreads();   // previous tap's frag reads done before overwrite

        // ---- stage B tile [c][o], vectorized, conflict-free ----
        {
            const float4* wsrc = (const float4*)(g_wr + tap*CC*OO);
            #pragma unroll
            for (int i = 0; i < 4; i++) {
                int idx4 = t + i*256;            // 1024 float4s
                float4 wv = wsrc[idx4];
                int c = idx4 >> 4;
                int o4 = (idx4 & 15) * 4;
                *(float4*)&Bs[c*B_PITCH + o4] = wv;
            }
        }

        // ---- gather A tile: 8 iterations of 2 positions per warp ----
        int ki = tap / 3, kj = tap % 3;
        #pragma unroll
        for (int it = 0; it < 8; it++) {
            int pos = wid*16 + it*2 + pp;        // 0..127 (== w coordinate)
            const float* omp = g_om + ((size_t)b*HW + p0 + pos)*27;
            float dy = __ldg(omp + 2*tap);
            float dx = __ldg(omp + 2*tap + 1);
            float msk = __ldg(omp + 18 + tap);
            float ysf = (float)(h - 1 + ki) + dy;
            float xsf = (float)(pos - 1 + kj) + dx;
            float y0f = floorf(ysf), x0f = floorf(xsf);
            float fy = ysf - y0f, fx = xsf - x0f;
            int y0 = (int)y0f, x0 = (int)x0f;
            int y1 = y0 + 1, x1 = x0 + 1;
            float gy = 1.f - fy, gx = 1.f - fx;
            float w00 = gy*gx*msk, w01 = gy*fx*msk, w10 = fy*gx*msk, w11 = fy*fx*msk;
            bool vy0 = (unsigned)y0 < HH, vy1 = (unsigned)y1 < HH;
            bool vx0 = (unsigned)x0 < WW, vx1 = (unsigned)x1 < WW;
            w00 = (vy0 && vx0) ? w00 : 0.f;
            w01 = (vy0 && vx1) ? w01 : 0.f;
            w10 = (vy1 && vx0) ? w10 : 0.f;
            w11 = (vy1 && vx1) ? w11 : 0.f;
            int cy0 = min(max(y0, 0), HH-1), cy1 = min(max(y1, 0), HH-1);
            int cx0 = min(max(x0, 0), WW-1), cx1 = min(max(x1, 0), WW-1);
            int cc4 = cl * 4;
            float4 a0 = *(const float4*)(xtb + (cy0*WW + cx0)*CC + cc4);
            float4 a1 = *(const float4*)(xtb + (cy0*WW + cx1)*CC + cc4);
            float4 a2 = *(const float4*)(xtb + (cy1*WW + cx0)*CC + cc4);
            float4 a3 = *(const float4*)(xtb + (cy1*WW + cx1)*CC + cc4);
            uint4 v;
            v.x = f2tf32(w00*a0.x + w01*a1.x + w10*a2.x + w11*a3.x);
            v.y = f2tf32(w00*a0.y + w01*a1.y + w10*a2.y + w11*a3.y);
            v.z = f2tf32(w00*a0.z + w01*a1.z + w10*a2.z + w11*a3.z);
            v.w = f2tf32(w00*a0.w + w01*a1.w + w10*a2.w + w11*a3.w);
            *(uint4*)&As[pos*A_PITCH + cc4] = v;
        }
        __syncthreads();

        // ---- 8 k-steps of m16n8k8 per warp: 32x32 warp tile ----
        #pragma unroll
        for (int ks = 0; ks < 8; ks++) {
            int k0 = ks*8;
            uint32_t afr[2][4];
            #pragma unroll
            for (int mt = 0; mt < 2; mt++) {
                int r = m0 + mt*16 + gid;
                afr[mt][0] = __float_as_uint(As[r*A_PITCH + k0 + tig]);
                afr[mt][1] = __float_as_uint(As[(r+8)*A_PITCH + k0 + tig]);
                afr[mt][2] = __float_as_uint(As[r*A_PITCH + k0 + tig + 4]);
                afr[mt][3] = __float_as_uint(As[(r+8)*A_PITCH + k0 + tig + 4]);
            }
            uint32_t bfr[4][2];
            #pragma unroll
            for (int nt = 0; nt < 4; nt++) {
                int n = n0 + nt*8 + gid;
                bfr[nt][0] = __float_as_uint(Bs[(k0 + tig)*B_PITCH + n]);
                bfr[nt][1] = __float_as_uint(Bs[(k0 + tig + 4)*B_PITCH + n]);
            }
            #pragma unroll
            for (int mt = 0; mt < 2; mt++)
                #pragma unroll
                for (int nt = 0; nt < 4; nt++)
                    mma8(acc[mt][nt], afr[mt], bfr[nt]);
        }
    }

    // ---- epilogue: frags -> smem [o][pos] (pitch 132) -> coalesced stores ----
    __syncthreads();
    #pragma unroll
    for (int mt = 0; mt < 2; mt++)
        #pragma unroll
        for (int nt = 0; nt < 4; nt++) {
            int row = m0 + mt*16 + gid;
            int col = n0 + nt*8 + tig*2;
            As[col*132 + row]       = acc[mt][nt][0];
            As[(col+1)*132 + row]   = acc[mt][nt][1];
            As[col*132 + row + 8]   = acc[mt][nt][2];
            As[(col+1)*132 + row + 8] = acc[mt][nt][3];
        }
    __syncthreads();
    #pragma unroll
    for (int i = 0; i < 8; i++) {
        int idx = t + i*256;          // 2048 float4s
        int o = idx >> 5, p4 = idx & 31;
        float4 v = *(float4*)&As[o*132 + p4*4];
        float bv = __ldg(&bias[o]);
        v.x += bv; v.y += bv; v.z += bv; v.w += bv;
        *(float4*)&out[((size_t)(b*OO + o))*HW + p0 + p4*4] = v;
    }
}

// ---------------- Kernel C2: BN batch-stat pass over out ----------------
__global__ __launch_bounds__(256) void stats_pass_kernel(const float* __restrict__ out) {
    int bo = blockIdx.x;             // b*64 + o
    int o = bo & 63;
    const float4* p = (const float4*)(out + (size_t)bo*HW);
    float s = 0.f, q = 0.f;
    for (int i = threadIdx.x; i < HW/4; i += 256) {
        float4 v = p[i];
        s += v.x + v.y + v.z + v.w;
        q += v.x*v.x + v.y*v.y + v.z*v.z + v.w*v.w;
    }
    #pragma unroll
    for (int off = 16; off; off >>= 1) {
        s += __shfl_down_sync(0xffffffffu, s, off);
        q += __shfl_down_sync(0xffffffffu, q, off);
    }
    __shared__ float ss[8], sq[8];
    if ((threadIdx.x & 31) == 0) { ss[threadIdx.x >> 5] = s; sq[threadIdx.x >> 5] = q; }
    __syncthreads();
    if (threadIdx.x == 0) {
        float S = 0.f, Q = 0.f;
        #pragma unroll
        for (int i = 0; i < 8; i++) { S += ss[i]; Q += sq[i]; }
        atomicAdd(&g_sum[o], S);
        atomicAdd(&g_sq[o], Q);
    }
}

// ---------------- Kernel D: finalize BN stats ----------------
__global__ void stats_kernel(const float* __restrict__ gamma,
                             const float* __restrict__ beta) {
    int o = threadIdx.x;
    float n = (float)NPOS;
    float mean = g_sum[o] / n;
    float var  = g_sq[o] / n - mean*mean;
    float sc = gamma[o] * rsqrtf(var + 1e-5f);
    g_scale[o] = sc;
    g_shift[o] = beta[o] - mean*sc;
}

// ---------------- Kernel E: BN apply + ReLU ----------------
__global__ void bn_relu_kernel(float* __restrict__ out) {
    int i = blockIdx.x*blockDim.x + threadIdx.x;
    if (i < (BB*OO*HW)/4) {
        float4 v = ((float4*)out)[i];
        int o = ((i*4) >> 14) & 63;
        float sc = g_scale[o], sh = g_shift[o];
        v.x = fmaxf(fmaf(v.x, sc, sh), 0.f);
        v.y = fmaxf(fmaf(v.y, sc, sh), 0.f);
        v.z = fmaxf(fmaf(v.z, sc, sh), 0.f);
        v.w = fmaxf(fmaf(v.w, sc, sh), 0.f);
        ((float4*)out)[i] = v;
    }
}

extern "C" void kernel_launch(void* const* d_in, const int* in_sizes, int n_in,
                              void* d_out, int out_size) {
    const float* x  = (const float*)d_in[0];
    const float* ow = (const float*)d_in[1];
    const float* ob = (const float*)d_in[2];
    const float* wt = (const float*)d_in[3];
    const float* bs = (const float*)d_in[4];
    const float* gm = (const float*)d_in[5];
    const float* bt = (const float*)d_in[6];
    float* out = (float*)d_out;

    cudaFuncSetAttribute(offset_conv_kernel,
                         cudaFuncAttributeMaxDynamicSharedMemorySize, 576*28*4);
    cudaFuncSetAttribute(main_kernel,
                         cudaFuncAttributeMaxDynamicSharedMemorySize, SMEM_FLOATS*4);

    prep_kernel<<<BB*HH, 256>>>(x, wt);
    offset_conv_kernel<<<NPOS/256, 256, 576*28*4>>>(x, ow, ob);
    main_kernel<<<BB*128, 256, SMEM_FLOATS*4>>>(bs, out);
    stats_pass_kernel<<<BB*OO, 256>>>(out);
    stats_kernel<<<1, OO>>>(gm, bt);
    bn_relu_kernel<<<(BB*OO*HW/4 + 255)/256, 256>>>(out);
}

// round 5
// speedup vs baseline: 1.8236x; 1.0013x over previous
#include <cuda_runtime.h>
#include <math.h>
#include <stdint.h>

#define BB 4
#define CC 64
#define HH 128
#define WW 128
#define OO 64
#define HW (HH*WW)          // 16384
#define NPOS (BB*HW)        // 65536

#define A_PITCH 68          // floats; 68 mod 32 = 4 -> conflict-free A frags
#define B_PITCH 72          // floats; 72 mod 32 = 8 -> conflict-free B frags
#define SMEM_FLOATS (128*A_PITCH + 64*B_PITCH)   // 8704 + 4608 = 13312 -> 53248 B

// -------- scratch (device globals; no allocation allowed) --------
__device__ float g_xt[BB*HH*WW*CC];        // x transposed to [b][h][w][c]
__device__ float g_om[(size_t)NPOS*27];    // offsets(18) + sigmoid(mask)(9), per-pos
__device__ float g_wr[9*CC*OO];            // weight reordered [tap][c][o], tf32-rounded
__device__ float g_sum[OO];
__device__ float g_sq[OO];
__device__ float g_scale[OO];
__device__ float g_shift[OO];

__device__ __forceinline__ uint32_t f2tf32(float f) {
    uint32_t u;
    asm("cvt.rna.tf32.f32 %0, %1;" : "=r"(u) : "f"(f));
    return u;
}

__device__ __forceinline__ void mma8(float* d, const uint32_t* a, const uint32_t* b) {
    asm volatile(
        "mma.sync.aligned.m16n8k8.row.col.f32.tf32.tf32.f32 "
        "{%0,%1,%2,%3}, {%4,%5,%6,%7}, {%8,%9}, {%0,%1,%2,%3};"
        : "+f"(d[0]), "+f"(d[1]), "+f"(d[2]), "+f"(d[3])
        : "r"(a[0]), "r"(a[1]), "r"(a[2]), "r"(a[3]), "r"(b[0]), "r"(b[1]));
}

// ---------------- Kernel A: transpose + weight reorder + zero stats ----------------
__global__ void prep_kernel(const float* __restrict__ x,
                            const float* __restrict__ weight) {
    __shared__ float s[CC*129];
    int b = blockIdx.x >> 7;
    int h = blockIdx.x & 127;
    int tid = threadIdx.x;
    for (int i = tid; i < CC*WW; i += 256) {
        int c = i >> 7, w = i & 127;
        s[c*129 + w] = x[((b*CC + c)*HH + h)*WW + w];
    }
    __syncthreads();
    for (int i = tid; i < WW*CC; i += 256) {
        int w = i >> 6, c = i & 63;
        g_xt[(((b*HH) + h)*WW + w)*CC + c] = s[c*129 + w];
    }
    if (blockIdx.x == 0) {
        // reorder main conv weight [O][C][3][3] -> [tap][c][o], tf32-rounded
        for (int i = tid; i < 9*CC*OO; i += 256) {
            int o = i / (CC*9);
            int r = i % (CC*9);
            int c = r / 9;
            int t = r % 9;
            g_wr[(t*CC + c)*OO + o] = __uint_as_float(f2tf32(weight[i]));
        }
        if (tid < OO) { g_sum[tid] = 0.f; g_sq[tid] = 0.f; }
    }
}

// ---------------- Kernel B: 3x3 offset/mask conv (27 out channels) ----------------
__global__ __launch_bounds__(256) void offset_conv_kernel(
        const float* __restrict__ x,
        const float* __restrict__ ow,
        const float* __restrict__ ob) {
    extern __shared__ float ws[];  // [c*9+t][28]
    int tid = threadIdx.x;
    for (int i = tid; i < 27*576; i += 256) {
        int j = i / 576, r = i % 576;
        ws[r*28 + j] = ow[i];
    }
    for (int i = tid; i < 576; i += 256) ws[i*28 + 27] = 0.f;
    __syncthreads();

    int pos = blockIdx.x*256 + tid;
    int b = pos >> 14, p = pos & 16383;
    int h = p >> 7, w = p & 127;

    float acc[28];
    #pragma unroll
    for (int j = 0; j < 28; j++) acc[j] = 0.f;

    const float* xb = x + (size_t)b*CC*HW;
    #pragma unroll 1
    for (int t = 0; t < 9; t++) {
        int y = h + t/3 - 1, xw = w + t%3 - 1;
        if ((unsigned)y < HH && (unsigned)xw < WW) {
            const float* xp = xb + y*WW + xw;
            #pragma unroll 4
            for (int c = 0; c < CC; c++) {
                float v = __ldg(xp + c*HW);
                const float4* wp = (const float4*)&ws[(c*9 + t)*28];
                #pragma unroll
                for (int q = 0; q < 7; q++) {
                    float4 wv = wp[q];
                    acc[q*4+0] += v*wv.x;
                    acc[q*4+1] += v*wv.y;
                    acc[q*4+2] += v*wv.z;
                    acc[q*4+3] += v*wv.w;
                }
            }
        }
    }
    float* omp = &g_om[(size_t)pos*27];
    #pragma unroll
    for (int j = 0; j < 27; j++) {
        float v = acc[j] + __ldg(&ob[j]);
        if (j >= 18) v = 1.f/(1.f + __expf(-v));
        omp[j] = v;
    }
}

// ---------------- Kernel C: deformable gather + mma.sync tf32 GEMM ----------------
// One CTA = one image row (128 positions) x all 64 output channels.
// As: [128 pos][64 ch] pitch 68; Bs: [64 c][64 o] pitch 72 (per tap).
// 8 warps in 4x2: warp tile 32 pos x 32 o, m16n8k8 tf32 fragments.
__global__ __launch_bounds__(256, 2) void main_kernel(const float* __restrict__ bias,
                                                      float* __restrict__ out) {
    extern __shared__ float sm[];
    float* As = sm;                  // 128*68 floats
    float* Bs = sm + 128*A_PITCH;    // 64*72 floats

    int t = threadIdx.x;
    int wid = t >> 5, lane = t & 31;
    int b = blockIdx.x >> 7;
    int h = blockIdx.x & 127;
    int p0 = h * 128;

    // gather role: warp -> 16 positions, lane -> (pos parity, channel group)
    int pp = lane >> 4;          // 0..1
    int cl = lane & 15;          // channel group: floats cl*4..cl*4+3
    const float* xtb = g_xt + (size_t)b*HW*CC;

    // gemm role
    int m0 = (wid & 3) * 32;
    int n0 = (wid >> 2) * 32;
    int gid = lane >> 2, tig = lane & 3;

    float acc[2][4][4];
    #pragma unroll
    for (int mt = 0; mt < 2; mt++)
        #pragma unroll
        for (int nt = 0; nt < 4; nt++)
            #pragma unroll
            for (int q = 0; q < 4; q++) acc[mt][nt][q] = 0.f;

    #pragma unroll 1
    for (int tap = 0; tap < 9; tap++) {
        __syncthreads();   // previous tap's frag reads done before overwrite

        // ---- stage B tile [c][o], vectorized, conflict-free ----
        {
            const float4* wsrc = (const float4*)(g_wr + tap*CC*OO);
            #pragma unroll
            for (int i = 0; i < 4; i++) {
                int idx4 = t + i*256;            // 1024 float4s
                float4 wv = wsrc[idx4];
                int c = idx4 >> 4;
                int o4 = (idx4 & 15) * 4;
                *(float4*)&Bs[c*B_PITCH + o4] = wv;
            }
        }

        // ---- gather A tile: 8 iterations of 2 positions per warp ----
        int ki = tap / 3, kj = tap % 3;
        #pragma unroll
        for (int it = 0; it < 8; it++) {
            int pos = wid*16 + it*2 + pp;        // 0..127 (== w coordinate)
            const float* omp = g_om + ((size_t)b*HW + p0 + pos)*27;
            float dy = __ldg(omp + 2*tap);
            float dx = __ldg(omp + 2*tap + 1);
            float msk = __ldg(omp + 18 + tap);
            float ysf = (float)(h - 1 + ki) + dy;
            float xsf = (float)(pos - 1 + kj) + dx;
            float y0f = floorf(ysf), x0f = floorf(xsf);
            float fy = ysf - y0f, fx = xsf - x0f;
            int y0 = (int)y0f, x0 = (int)x0f;
            int y1 = y0 + 1, x1 = x0 + 1;
            float gy = 1.f - fy, gx = 1.f - fx;
            float w00 = gy*gx*msk, w01 = gy*fx*msk, w10 = fy*gx*msk, w11 = fy*fx*msk;
            bool vy0 = (unsigned)y0 < HH, vy1 = (unsigned)y1 < HH;
            bool vx0 = (unsigned)x0 < WW, vx1 = (unsigned)x1 < WW;
            w00 = (vy0 && vx0) ? w00 : 0.f;
            w01 = (vy0 && vx1) ? w01 : 0.f;
            w10 = (vy1 && vx0) ? w10 : 0.f;
            w11 = (vy1 && vx1) ? w11 : 0.f;
            int cy0 = min(max(y0, 0), HH-1), cy1 = min(max(y1, 0), HH-1);
            int cx0 = min(max(x0, 0), WW-1), cx1 = min(max(x1, 0), WW-1);
            int cc4 = cl * 4;
            float4 a0 = *(const float4*)(xtb + (cy0*WW + cx0)*CC + cc4);
            float4 a1 = *(const float4*)(xtb + (cy0*WW + cx1)*CC + cc4);
            float4 a2 = *(const float4*)(xtb + (cy1*WW + cx0)*CC + cc4);
            float4 a3 = *(const float4*)(xtb + (cy1*WW + cx1)*CC + cc4);
            uint4 v;
            v.x = f2tf32(w00*a0.x + w01*a1.x + w10*a2.x + w11*a3.x);
            v.y = f2tf32(w00*a0.y + w01*a1.y + w10*a2.y + w11*a3.y);
            v.z = f2tf32(w00*a0.z + w01*a1.z + w10*a2.z + w11*a3.z);
            v.w = f2tf32(w00*a0.w + w01*a1.w + w10*a2.w + w11*a3.w);
            *(uint4*)&As[pos*A_PITCH + cc4] = v;
        }
        __syncthreads();

        // ---- 8 k-steps of m16n8k8 per warp: 32x32 warp tile ----
        #pragma unroll
        for (int ks = 0; ks < 8; ks++) {
            int k0 = ks*8;
            uint32_t afr[2][4];
            #pragma unroll
            for (int mt = 0; mt < 2; mt++) {
                int r = m0 + mt*16 + gid;
                afr[mt][0] = __float_as_uint(As[r*A_PITCH + k0 + tig]);
                afr[mt][1] = __float_as_uint(As[(r+8)*A_PITCH + k0 + tig]);
                afr[mt][2] = __float_as_uint(As[r*A_PITCH + k0 + tig + 4]);
                afr[mt][3] = __float_as_uint(As[(r+8)*A_PITCH + k0 + tig + 4]);
            }
            uint32_t bfr[4][2];
            #pragma unroll
            for (int nt = 0; nt < 4; nt++) {
                int n = n0 + nt*8 + gid;
                bfr[nt][0] = __float_as_uint(Bs[(k0 + tig)*B_PITCH + n]);
                bfr[nt][1] = __float_as_uint(Bs[(k0 + tig + 4)*B_PITCH + n]);
            }
            #pragma unroll
            for (int mt = 0; mt < 2; mt++)
                #pragma unroll
                for (int nt = 0; nt < 4; nt++)
                    mma8(acc[mt][nt], afr[mt], bfr[nt]);
        }
    }

    // ---- epilogue: frags -> smem [o][pos] (pitch 132) -> coalesced stores ----
    __syncthreads();
    #pragma unroll
    for (int mt = 0; mt < 2; mt++)
        #pragma unroll
        for (int nt = 0; nt < 4; nt++) {
            int row = m0 + mt*16 + gid;
            int col = n0 + nt*8 + tig*2;
            As[col*132 + row]       = acc[mt][nt][0];
            As[(col+1)*132 + row]   = acc[mt][nt][1];
            As[col*132 + row + 8]   = acc[mt][nt][2];
            As[(col+1)*132 + row + 8] = acc[mt][nt][3];
        }
    __syncthreads();
    #pragma unroll
    for (int i = 0; i < 8; i++) {
        int idx = t + i*256;          // 2048 float4s
        int o = idx >> 5, p4 = idx & 31;
        float4 v = *(float4*)&As[o*132 + p4*4];
        float bv = __ldg(&bias[o]);
        v.x += bv; v.y += bv; v.z += bv; v.w += bv;
        *(float4*)&out[((size_t)(b*OO + o))*HW + p0 + p4*4] = v;
    }
}

// ---------------- Kernel C2: BN batch-stat pass over out ----------------
__global__ __launch_bounds__(256) void stats_pass_kernel(const float* __restrict__ out) {
    int bo = blockIdx.x;             // b*64 + o
    int o = bo & 63;
    const float4* p = (const float4*)(out + (size_t)bo*HW);
    float s = 0.f, q = 0.f;
    for (int i = threadIdx.x; i < HW/4; i += 256) {
        float4 v = p[i];
        s += v.x + v.y + v.z + v.w;
        q += v.x*v.x + v.y*v.y + v.z*v.z + v.w*v.w;
    }
    #pragma unroll
    for (int off = 16; off; off >>= 1) {
        s += __shfl_down_sync(0xffffffffu, s, off);
        q += __shfl_down_sync(0xffffffffu, q, off);
    }
    __shared__ float ss[8], sq[8];
    if ((threadIdx.x & 31) == 0) { ss[threadIdx.x >> 5] = s; sq[threadIdx.x >> 5] = q; }
    __syncthreads();
    if (threadIdx.x == 0) {
        float S = 0.f, Q = 0.f;
        #pragma unroll
        for (int i = 0; i < 8; i++) { S += ss[i]; Q += sq[i]; }
        atomicAdd(&g_sum[o], S);
        atomicAdd(&g_sq[o], Q);
    }
}

// ---------------- Kernel D: finalize BN stats ----------------
__global__ void stats_kernel(const float* __restrict__ gamma,
                             const float* __restrict__ beta) {
    int o = threadIdx.x;
    float n = (float)NPOS;
    float mean = g_sum[o] / n;
    float var  = g_sq[o] / n - mean*mean;
    float sc = gamma[o] * rsqrtf(var + 1e-5f);
    g_scale[o] = sc;
    g_shift[o] = beta[o] - mean*sc;
}

// ---------------- Kernel E: BN apply + ReLU ----------------
__global__ void bn_relu_kernel(float* __restrict__ out) {
    int i = blockIdx.x*blockDim.x + threadIdx.x;
    if (i < (BB*OO*HW)/4) {
        float4 v = ((float4*)out)[i];
        int o = ((i*4) >> 14) & 63;
        float sc = g_scale[o], sh = g_shift[o];
        v.x = fmaxf(fmaf(v.x, sc, sh), 0.f);
        v.y = fmaxf(fmaf(v.y, sc, sh), 0.f);
        v.z = fmaxf(fmaf(v.z, sc, sh), 0.f);
        v.w = fmaxf(fmaf(v.w, sc, sh), 0.f);
        ((float4*)out)[i] = v;
    }
}

extern "C" void kernel_launch(void* const* d_in, const int* in_sizes, int n_in,
                              void* d_out, int out_size) {
    const float* x  = (const float*)d_in[0];
    const float* ow = (const float*)d_in[1];
    const float* ob = (const float*)d_in[2];
    const float* wt = (const float*)d_in[3];
    const float* bs = (const float*)d_in[4];
    const float* gm = (const float*)d_in[5];
    const float* bt = (const float*)d_in[6];
    float* out = (float*)d_out;

    cudaFuncSetAttribute(offset_conv_kernel,
                         cudaFuncAttributeMaxDynamicSharedMemorySize, 576*28*4);
    cudaFuncSetAttribute(main_kernel,
                         cudaFuncAttributeMaxDynamicSharedMemorySize, SMEM_FLOATS*4);

    prep_kernel<<<BB*HH, 256>>>(x, wt);
    offset_conv_kernel<<<NPOS/256, 256, 576*28*4>>>(x, ow, ob);
    main_kernel<<<BB*128, 256, SMEM_FLOATS*4>>>(bs, out);
    stats_pass_kernel<<<BB*OO, 256>>>(out);
    stats_kernel<<<1, OO>>>(gm, bt);
    bn_relu_kernel<<<(BB*OO*HW/4 + 255)/256, 256>>>(out);
}

// round 6
// speedup vs baseline: 1.8359x; 1.0068x over previous
#include <cuda_runtime.h>
#include <math.h>
#include <stdint.h>

#define BB 4
#define CC 64
#define HH 128
#define WW 128
#define OO 64
#define HW (HH*WW)          // 16384
#define NPOS (BB*HW)        // 65536

#define A_PITCH 68          // floats; 68 mod 32 = 4 -> conflict-free A frags
#define B_PITCH 72          // floats; 72 mod 32 = 8 -> conflict-free B frags
#define SMEM_FLOATS (128*A_PITCH + 64*B_PITCH)   // 8704 + 4608 = 13312 -> 53248 B

// -------- scratch (device globals; no allocation allowed) --------
__device__ float g_xt[BB*HH*WW*CC];        // x transposed to [b][h][w][c]
__device__ float g_om[(size_t)NPOS*27];    // offsets(18) + sigmoid(mask)(9), per-pos
__device__ float g_wr[9*CC*OO];            // weight reordered [tap][c][o], tf32-rounded
__device__ float g_sum[OO];
__device__ float g_sq[OO];
__device__ float g_scale[OO];
__device__ float g_shift[OO];

__device__ __forceinline__ uint32_t f2tf32(float f) {
    uint32_t u;
    asm("cvt.rna.tf32.f32 %0, %1;" : "=r"(u) : "f"(f));
    return u;
}

__device__ __forceinline__ void mma8(float* d, const uint32_t* a, const uint32_t* b) {
    asm volatile(
        "mma.sync.aligned.m16n8k8.row.col.f32.tf32.tf32.f32 "
        "{%0,%1,%2,%3}, {%4,%5,%6,%7}, {%8,%9}, {%0,%1,%2,%3};"
        : "+f"(d[0]), "+f"(d[1]), "+f"(d[2]), "+f"(d[3])
        : "r"(a[0]), "r"(a[1]), "r"(a[2]), "r"(a[3]), "r"(b[0]), "r"(b[1]));
}

// ---------------- Kernel A: transpose + weight reorder + zero stats ----------------
__global__ void prep_kernel(const float* __restrict__ x,
                            const float* __restrict__ weight) {
    __shared__ float s[CC*129];
    int b = blockIdx.x >> 7;
    int h = blockIdx.x & 127;
    int tid = threadIdx.x;
    for (int i = tid; i < CC*WW; i += 256) {
        int c = i >> 7, w = i & 127;
        s[c*129 + w] = x[((b*CC + c)*HH + h)*WW + w];
    }
    __syncthreads();
    for (int i = tid; i < WW*CC; i += 256) {
        int w = i >> 6, c = i & 63;
        g_xt[(((b*HH) + h)*WW + w)*CC + c] = s[c*129 + w];
    }
    if (blockIdx.x == 0) {
        // reorder main conv weight [O][C][3][3] -> [tap][c][o], tf32-rounded
        for (int i = tid; i < 9*CC*OO; i += 256) {
            int o = i / (CC*9);
            int r = i % (CC*9);
            int c = r / 9;
            int t = r % 9;
            g_wr[(t*CC + c)*OO + o] = __uint_as_float(f2tf32(weight[i]));
        }
        if (tid < OO) { g_sum[tid] = 0.f; g_sq[tid] = 0.f; }
    }
}

// ---------------- Kernel B: 3x3 offset/mask conv (27 out channels) ----------------
__global__ __launch_bounds__(256) void offset_conv_kernel(
        const float* __restrict__ x,
        const float* __restrict__ ow,
        const float* __restrict__ ob) {
    extern __shared__ float ws[];  // [c*9+t][28]
    int tid = threadIdx.x;
    for (int i = tid; i < 27*576; i += 256) {
        int j = i / 576, r = i % 576;
        ws[r*28 + j] = ow[i];
    }
    for (int i = tid; i < 576; i += 256) ws[i*28 + 27] = 0.f;
    __syncthreads();

    int pos = blockIdx.x*256 + tid;
    int b = pos >> 14, p = pos & 16383;
    int h = p >> 7, w = p & 127;

    float acc[28];
    #pragma unroll
    for (int j = 0; j < 28; j++) acc[j] = 0.f;

    const float* xb = x + (size_t)b*CC*HW;
    #pragma unroll 1
    for (int t = 0; t < 9; t++) {
        int y = h + t/3 - 1, xw = w + t%3 - 1;
        if ((unsigned)y < HH && (unsigned)xw < WW) {
            const float* xp = xb + y*WW + xw;
            #pragma unroll 4
            for (int c = 0; c < CC; c++) {
                float v = __ldg(xp + c*HW);
                const float4* wp = (const float4*)&ws[(c*9 + t)*28];
                #pragma unroll
                for (int q = 0; q < 7; q++) {
                    float4 wv = wp[q];
                    acc[q*4+0] += v*wv.x;
                    acc[q*4+1] += v*wv.y;
                    acc[q*4+2] += v*wv.z;
                    acc[q*4+3] += v*wv.w;
                }
            }
        }
    }
    float* omp = &g_om[(size_t)pos*27];
    #pragma unroll
    for (int j = 0; j < 27; j++) {
        float v = acc[j] + __ldg(&ob[j]);
        if (j >= 18) v = 1.f/(1.f + __expf(-v));
        omp[j] = v;
    }
}

// ---------------- Kernel C: deformable gather + mma.sync tf32 GEMM ----------------
// One CTA = one image row (128 positions) x all 64 output channels.
// As: [128 pos][64 ch] pitch 68; Bs: [64 c][64 o] pitch 72 (per tap).
// 8 warps in 4x2: warp tile 32 pos x 32 o, m16n8k8 tf32 fragments.
__global__ __launch_bounds__(256, 2) void main_kernel(const float* __restrict__ bias,
                                                      float* __restrict__ out) {
    extern __shared__ float sm[];
    float* As = sm;                  // 128*68 floats
    float* Bs = sm + 128*A_PITCH;    // 64*72 floats

    int t = threadIdx.x;
    int wid = t >> 5, lane = t & 31;
    int b = blockIdx.x >> 7;
    int h = blockIdx.x & 127;
    int p0 = h * 128;

    // gather role: warp -> 16 positions, lane -> (pos parity, channel group)
    int pp = lane >> 4;          // 0..1
    int cl = lane & 15;          // channel group: floats cl*4..cl*4+3
    const float* xtb = g_xt + (size_t)b*HW*CC;

    // gemm role
    int m0 = (wid & 3) * 32;
    int n0 = (wid >> 2) * 32;
    int gid = lane >> 2, tig = lane & 3;

    float acc[2][4][4];
    #pragma unroll
    for (int mt = 0; mt < 2; mt++)
        #pragma unroll
        for (int nt = 0; nt < 4; nt++)
            #pragma unroll
            for (int q = 0; q < 4; q++) acc[mt][nt][q] = 0.f;

    #pragma unroll 1
    for (int tap = 0; tap < 9; tap++) {
        __syncthreads();   // previous tap's frag reads done before overwrite

        // ---- stage B tile [c][o], vectorized, conflict-free ----
        {
            const float4* wsrc = (const float4*)(g_wr + tap*CC*OO);
            #pragma unroll
            for (int i = 0; i < 4; i++) {
                int idx4 = t + i*256;            // 1024 float4s
                float4 wv = wsrc[idx4];
                int c = idx4 >> 4;
                int o4 = (idx4 & 15) * 4;
                *(float4*)&Bs[c*B_PITCH + o4] = wv;
            }
        }

        // ---- gather A tile: 8 iterations of 2 positions per warp ----
        int ki = tap / 3, kj = tap % 3;
        #pragma unroll
        for (int it = 0; it < 8; it++) {
            int pos = wid*16 + it*2 + pp;        // 0..127 (== w coordinate)
            const float* omp = g_om + ((size_t)b*HW + p0 + pos)*27;
            float dy = __ldg(omp + 2*tap);
            float dx = __ldg(omp + 2*tap + 1);
            float msk = __ldg(omp + 18 + tap);
            float ysf = (float)(h - 1 + ki) + dy;
            float xsf = (float)(pos - 1 + kj) + dx;
            float y0f = floorf(ysf), x0f = floorf(xsf);
            float fy = ysf - y0f, fx = xsf - x0f;
            int y0 = (int)y0f, x0 = (int)x0f;
            int y1 = y0 + 1, x1 = x0 + 1;
            float gy = 1.f - fy, gx = 1.f - fx;
            float w00 = gy*gx*msk, w01 = gy*fx*msk, w10 = fy*gx*msk, w11 = fy*fx*msk;
            bool vy0 = (unsigned)y0 < HH, vy1 = (unsigned)y1 < HH;
            bool vx0 = (unsigned)x0 < WW, vx1 = (unsigned)x1 < WW;
            w00 = (vy0 && vx0) ? w00 : 0.f;
            w01 = (vy0 && vx1) ? w01 : 0.f;
            w10 = (vy1 && vx0) ? w10 : 0.f;
            w11 = (vy1 && vx1) ? w11 : 0.f;
            int cy0 = min(max(y0, 0), HH-1), cy1 = min(max(y1, 0), HH-1);
            int cx0 = min(max(x0, 0), WW-1), cx1 = min(max(x1, 0), WW-1);
            int cc4 = cl * 4;
            float4 a0 = *(const float4*)(xtb + (cy0*WW + cx0)*CC + cc4);
            float4 a1 = *(const float4*)(xtb + (cy0*WW + cx1)*CC + cc4);
            float4 a2 = *(const float4*)(xtb + (cy1*WW + cx0)*CC + cc4);
            float4 a3 = *(const float4*)(xtb + (cy1*WW + cx1)*CC + cc4);
            uint4 v;
            v.x = f2tf32(w00*a0.x + w01*a1.x + w10*a2.x + w11*a3.x);
            v.y = f2tf32(w00*a0.y + w01*a1.y + w10*a2.y + w11*a3.y);
            v.z = f2tf32(w00*a0.z + w01*a1.z + w10*a2.z + w11*a3.z);
            v.w = f2tf32(w00*a0.w + w01*a1.w + w10*a2.w + w11*a3.w);
            *(uint4*)&As[pos*A_PITCH + cc4] = v;
        }
        __syncthreads();

        // ---- 8 k-steps of m16n8k8 per warp: 32x32 warp tile ----
        #pragma unroll
        for (int ks = 0; ks < 8; ks++) {
            int k0 = ks*8;
            uint32_t afr[2][4];
            #pragma unroll
            for (int mt = 0; mt < 2; mt++) {
                int r = m0 + mt*16 + gid;
                afr[mt][0] = __float_as_uint(As[r*A_PITCH + k0 + tig]);
                afr[mt][1] = __float_as_uint(As[(r+8)*A_PITCH + k0 + tig]);
                afr[mt][2] = __float_as_uint(As[r*A_PITCH + k0 + tig + 4]);
                afr[mt][3] = __float_as_uint(As[(r+8)*A_PITCH + k0 + tig + 4]);
            }
            uint32_t bfr[4][2];
            #pragma unroll
            for (int nt = 0; nt < 4; nt++) {
                int n = n0 + nt*8 + gid;
                bfr[nt][0] = __float_as_uint(Bs[(k0 + tig)*B_PITCH + n]);
                bfr[nt][1] = __float_as_uint(Bs[(k0 + tig + 4)*B_PITCH + n]);
            }
            #pragma unroll
            for (int mt = 0; mt < 2; mt++)
                #pragma unroll
                for (int nt = 0; nt < 4; nt++)
                    mma8(acc[mt][nt], afr[mt], bfr[nt]);
        }
    }

    // ---- epilogue: frags -> smem [o][pos] (pitch 132) -> coalesced stores ----
    __syncthreads();
    #pragma unroll
    for (int mt = 0; mt < 2; mt++)
        #pragma unroll
        for (int nt = 0; nt < 4; nt++) {
            int row = m0 + mt*16 + gid;
            int col = n0 + nt*8 + tig*2;
            As[col*132 + row]       = acc[mt][nt][0];
            As[(col+1)*132 + row]   = acc[mt][nt][1];
            As[col*132 + row + 8]   = acc[mt][nt][2];
            As[(col+1)*132 + row + 8] = acc[mt][nt][3];
        }
    __syncthreads();
    #pragma unroll
    for (int i = 0; i < 8; i++) {
        int idx = t + i*256;          // 2048 float4s
        int o = idx >> 5, p4 = idx & 31;
        float4 v = *(float4*)&As[o*132 + p4*4];
        float bv = __ldg(&bias[o]);
        v.x += bv; v.y += bv; v.z += bv; v.w += bv;
        *(float4*)&out[((size_t)(b*OO + o))*HW + p0 + p4*4] = v;
    }
}

// ---------------- Kernel C2: BN batch-stat pass over out ----------------
__global__ __launch_bounds__(256) void stats_pass_kernel(const float* __restrict__ out) {
    int bo = blockIdx.x;             // b*64 + o
    int o = bo & 63;
    const float4* p = (const float4*)(out + (size_t)bo*HW);
    float s = 0.f, q = 0.f;
    for (int i = threadIdx.x; i < HW/4; i += 256) {
        float4 v = p[i];
        s += v.x + v.y + v.z + v.w;
        q += v.x*v.x + v.y*v.y + v.z*v.z + v.w*v.w;
    }
    #pragma unroll
    for (int off = 16; off; off >>= 1) {
        s += __shfl_down_sync(0xffffffffu, s, off);
        q += __shfl_down_sync(0xffffffffu, q, off);
    }
    __shared__ float ss[8], sq[8];
    if ((threadIdx.x & 31) == 0) { ss[threadIdx.x >> 5] = s; sq[threadIdx.x >> 5] = q; }
    __syncthreads();
    if (threadIdx.x == 0) {
        float S = 0.f, Q = 0.f;
        #pragma unroll
        for (int i = 0; i < 8; i++) { S += ss[i]; Q += sq[i]; }
        atomicAdd(&g_sum[o], S);
        atomicAdd(&g_sq[o], Q);
    }
}

// ---------------- Kernel D: finalize BN stats ----------------
__global__ void stats_kernel(const float* __restrict__ gamma,
                             const float* __restrict__ beta) {
    int o = threadIdx.x;
    float n = (float)NPOS;
    float mean = g_sum[o] / n;
    float var  = g_sq[o] / n - mean*mean;
    float sc = gamma[o] * rsqrtf(var + 1e-5f);
    g_scale[o] = sc;
    g_shift[o] = beta[o] - mean*sc;
}

// ---------------- Kernel E: BN apply + ReLU ----------------
__global__ void bn_relu_kernel(float* __restrict__ out) {
    int i = blockIdx.x*blockDim.x + threadIdx.x;
    if (i < (BB*OO*HW)/4) {
        float4 v = ((float4*)out)[i];
        int o = ((i*4) >> 14) & 63;
        float sc = g_scale[o], sh = g_shift[o];
        v.x = fmaxf(fmaf(v.x, sc, sh), 0.f);
        v.y = fmaxf(fmaf(v.y, sc, sh), 0.f);
        v.z = fmaxf(fmaf(v.z, sc, sh), 0.f);
        v.w = fmaxf(fmaf(v.w, sc, sh), 0.f);
        ((float4*)out)[i] = v;
    }
}

extern "C" void kernel_launch(void* const* d_in, const int* in_sizes, int n_in,
                              void* d_out, int out_size) {
    const float* x  = (const float*)d_in[0];
    const float* ow = (const float*)d_in[1];
    const float* ob = (const float*)d_in[2];
    const float* wt = (const float*)d_in[3];
    const float* bs = (const float*)d_in[4];
    const float* gm = (const float*)d_in[5];
    const float* bt = (const float*)d_in[6];
    float* out = (float*)d_out;

    cudaFuncSetAttribute(offset_conv_kernel,
                         cudaFuncAttributeMaxDynamicSharedMemorySize, 576*28*4);
    cudaFuncSetAttribute(main_kernel,
                         cudaFuncAttributeMaxDynamicSharedMemorySize, SMEM_FLOATS*4);

    prep_kernel<<<BB*HH, 256>>>(x, wt);
    offset_conv_kernel<<<NPOS/256, 256, 576*28*4>>>(x, ow, ob);
    main_kernel<<<BB*128, 256, SMEM_FLOATS*4>>>(bs, out);
    stats_pass_kernel<<<BB*OO, 256>>>(out);
    stats_kernel<<<1, OO>>>(gm, bt);
    bn_relu_kernel<<<(BB*OO*HW/4 + 255)/256, 256>>>(out);
}